// round 6
// baseline (speedup 1.0000x reference)
#include <cuda_runtime.h>
#include <math.h>

#define BIGV   100000000.0f
#define GAMMA_ 0.05f
#define INVG_  20.0f
#define WARPP  256.0f
#define K_     4
#define B_     8
#define KB_    32
#define N_     800
#define C_     80
#define S_     128
#define Z_     32

// ---- scratch (device globals; no runtime allocation) ----
__device__ float g_sx[(size_t)KB_ * N_ * C_];   // sigmoid(mel_iters)
__device__ float g_sy[(size_t)B_  * N_ * C_];   // sigmoid(mel_targets)
__device__ float g_x2[KB_ * N_];                // row norms of sx
__device__ float g_y2[B_  * N_];                // row norms of sy
__device__ float g_D [(size_t)KB_ * N_ * N_];   // distance matrices
__device__ float g_d [KB_];                     // DTW costs

// ============================================================
// Kernel 1: sigmoid + squared row norms. One warp per row.
// ============================================================
__global__ void prep_kernel(const float* __restrict__ mel_iters,
                            const float* __restrict__ mel_targets) {
    int wid  = (blockIdx.x * blockDim.x + threadIdx.x) >> 5;
    int lane = threadIdx.x & 31;
    const int xrows = KB_ * N_;
    const int total = xrows + B_ * N_;
    if (wid >= total) return;

    const float* src;
    float* dst;
    float* nrm;
    if (wid < xrows) {
        src = mel_iters + (size_t)wid * C_;
        dst = g_sx      + (size_t)wid * C_;
        nrm = g_x2 + wid;
    } else {
        int r = wid - xrows;
        src = mel_targets + (size_t)r * C_;
        dst = g_sy        + (size_t)r * C_;
        nrm = g_y2 + r;
    }
    float acc = 0.f;
    for (int c = lane; c < C_; c += 32) {
        float v = src[c];
        float s = 1.f / (1.f + expf(-v));
        dst[c] = s;
        acc += s * s;
    }
    #pragma unroll
    for (int o = 16; o; o >>= 1) acc += __shfl_xor_sync(0xffffffffu, acc, o);
    if (lane == 0) *nrm = acc;
}

// ============================================================
// Kernel 2: D[kb][n][m] = x2[n] + y2[m] - 2 * <sx[n], sy[m]>
// (identical to the proven 970us version)
// ============================================================
__global__ void __launch_bounds__(256) dist_gemm_kernel() {
    __shared__ float sA[80 * 65];
    __shared__ float sB[80 * 65];

    const int kb = blockIdx.z;
    const int b  = kb & 7;
    const int m0 = blockIdx.x * 64;
    const int n0 = blockIdx.y * 64;
    const int t  = threadIdx.x;

    const float* xbase = g_sx + (size_t)kb * N_ * C_ + (size_t)n0 * C_;
    const float* ybase = g_sy + (size_t)b  * N_ * C_ + (size_t)m0 * C_;

    for (int e = t; e < 64 * 80; e += 256) {
        int r = e / 80;
        int c = e - r * 80;
        float xv = (n0 + r < N_) ? xbase[r * C_ + c] : 0.f;
        float yv = (m0 + r < N_) ? ybase[r * C_ + c] : 0.f;
        sA[c * 65 + r] = xv;
        sB[c * 65 + r] = yv;
    }
    __syncthreads();

    const int tx = t & 15;
    const int ty = t >> 4;

    float acc[4][4];
    #pragma unroll
    for (int i = 0; i < 4; i++)
        #pragma unroll
        for (int j = 0; j < 4; j++) acc[i][j] = 0.f;

    #pragma unroll 8
    for (int k = 0; k < 80; k++) {
        float a[4], bb[4];
        #pragma unroll
        for (int i = 0; i < 4; i++) a[i]  = sA[k * 65 + ty * 4 + i];
        #pragma unroll
        for (int j = 0; j < 4; j++) bb[j] = sB[k * 65 + tx * 4 + j];
        #pragma unroll
        for (int i = 0; i < 4; i++)
            #pragma unroll
            for (int j = 0; j < 4; j++)
                acc[i][j] = fmaf(a[i], bb[j], acc[i][j]);
    }

    float* Dp = g_D + (size_t)kb * N_ * N_;
    #pragma unroll
    for (int i = 0; i < 4; i++) {
        int n = n0 + ty * 4 + i;
        if (n >= N_) continue;
        float xn = g_x2[kb * N_ + n];
        int mbase = m0 + tx * 4;
        if (mbase + 3 < N_) {
            float4 v;
            v.x = xn + g_y2[b * N_ + mbase + 0] - 2.f * acc[i][0];
            v.y = xn + g_y2[b * N_ + mbase + 1] - 2.f * acc[i][1];
            v.z = xn + g_y2[b * N_ + mbase + 2] - 2.f * acc[i][2];
            v.w = xn + g_y2[b * N_ + mbase + 3] - 2.f * acc[i][3];
            *reinterpret_cast<float4*>(&Dp[(size_t)n * N_ + mbase]) = v;
        } else {
            #pragma unroll
            for (int j = 0; j < 4; j++) {
                int m = mbase + j;
                if (m < N_)
                    Dp[(size_t)n * N_ + m] = xn + g_y2[b * N_ + m] - 2.f * acc[i][j];
            }
        }
    }
}

// ============================================================
// Kernel 3: soft-DTW, warp-skewed pipeline (NO block barriers).
// Warp w owns rows [32w+1, 32w+32], lane l -> row 32w+l+1.
// DP values in registers; i-1 neighbor via shfl_up; warp
// boundary via smem ring + volatile progress counters.
// FIX vs R5: per-diagonal body (compute + register shift + ring
// publish) is guarded by warp-uniform d <= dend so the tail of
// the last 4-group cannot clobber one_r with BIGV.
// ============================================================
#define WPC_   25          // 800 / 32 warps
#define DEPTH_ 256         // ring depth (power of 2)
#define RM_    (DEPTH_ - 1)

__global__ void __launch_bounds__(800) dtw_kernel() {
    __shared__ volatile float ring[WPC_][DEPTH_];   // top-row value per warp per diag
    __shared__ volatile int   progress[WPC_];       // last diagonal fully published

    const int kb   = blockIdx.x;
    const int t    = threadIdx.x;
    const int w    = t >> 5;
    const int lane = t & 31;
    const int i    = 32 * w + lane + 1;             // my row (1-indexed)

    if (t < WPC_) progress[t] = 32 * t + 1;         // = dstart_w - 1
    __syncthreads();

    const int dstart    = 32 * w + 2;               // first diag with any valid cell
    const int dend      = 32 * w + 32 + N_;         // last diag (top row, j = N)
    const int prod_dend = 32 * w + N_;              // producer (w-1) top row's last valid diag

    const float* Drow = g_D + (size_t)kb * N_ * N_ + (size_t)(i - 1) * N_ - 1;
    #define CLAMP_J(jj) ( (jj) < 1 ? 1 : ((jj) > N_ ? N_ : (jj)) )

    float one_r = BIGV, two_r = BIGV;

    // prefetch D for first 4 diagonals
    float cur0, cur1, cur2, cur3;
    {
        int j = dstart - i;
        cur0 = __ldg(Drow + CLAMP_J(j + 0));
        cur1 = __ldg(Drow + CLAMP_J(j + 1));
        cur2 = __ldg(Drow + CLAMP_J(j + 2));
        cur3 = __ldg(Drow + CLAMP_J(j + 3));
    }

    for (int d0 = dstart; d0 <= dend; d0 += 4) {
        // ---- prefetch next group's D ----
        int jn = d0 + 4 - i;
        float nx0 = __ldg(Drow + CLAMP_J(jn + 0));
        float nx1 = __ldg(Drow + CLAMP_J(jn + 1));
        float nx2 = __ldg(Drow + CLAMP_J(jn + 2));
        float nx3 = __ldg(Drow + CLAMP_J(jn + 3));

        // ---- wait for producer warp (once per group) ----
        if (w > 0 && lane == 0) {
            int need = d0 + 2;                       // max slot this group reads
            if (need > prod_dend) need = prod_dend;
            while (progress[w - 1] < need) { }
            __threadfence_block();                   // acquire
        }
        // ---- backpressure: don't overwrite slots consumer still needs ----
        if (w < WPC_ - 1 && lane == 0) {
            int lim = d0 + 8 - DEPTH_;
            if (lim > 0) { while (progress[w + 1] < lim) { } }
        }

        #pragma unroll
        for (int r = 0; r < 4; r++) {
            int d = d0 + r;
            if (d <= dend) {                         // warp-uniform guard
                // boundary values for lane 0 (row i-1 = 32w, from warp w-1)
                float b_one = BIGV, b_two = BIGV;
                if (lane == 0) {
                    if (w == 0) {
                        b_two = (d == 2) ? 0.f : BIGV;   // R[0][0]=0, else BIG
                    } else {
                        if (d - 1 <= prod_dend) b_one = ring[w - 1][(d - 1) & RM_];
                        if (d - 2 <= prod_dend) b_two = ring[w - 1][(d - 2) & RM_];
                    }
                }
                float up_one = __shfl_up_sync(0xffffffffu, one_r, 1);
                float up_two = __shfl_up_sync(0xffffffffu, two_r, 1);
                if (lane == 0) { up_one = b_one; up_two = b_two; }

                int j = d - i;
                float rv = BIGV;
                if (j >= 1 && j <= N_) {
                    float a  = up_two;
                    float bu = up_one + WARPP;
                    float c  = one_r  + WARPP;
                    float m  = fminf(a, fminf(bu, c));
                    float sm = m;
                    float d1 = a - m, d2 = bu - m, d3 = c - m;
                    float second = d1 + d2 + d3 - fmaxf(d1, fmaxf(d2, d3));
                    if (second < 1.0f) {
                        sm = m - GAMMA_ * logf(expf(-d1 * INVG_) +
                                               expf(-d2 * INVG_) +
                                               expf(-d3 * INVG_));
                    }
                    float Dv = (r == 0) ? cur0 : (r == 1) ? cur1 : (r == 2) ? cur2 : cur3;
                    rv = Dv + sm;
                }
                two_r = one_r;
                one_r = rv;

                if (lane == 31) ring[w][d & RM_] = rv;   // publish top-row value
            }
        }

        // ---- publish progress (release) ----
        __threadfence_block();
        if (lane == 31) {
            int last = d0 + 3; if (last > dend) last = dend;
            progress[w] = last;
        }

        cur0 = nx0; cur1 = nx1; cur2 = nx2; cur3 = nx3;
    }

    // final cell: row N (warp WPC_-1, lane 31) at diag 2N -> one_r
    if (w == WPC_ - 1 && lane == 31) g_d[kb] = one_r;
    #undef CLAMP_J
}

// ============================================================
// Kernel 4: finalize scalar losses (parallel, measured 6.5us).
// ============================================================
__global__ void finalize_kernel(const int* __restrict__ mel_lens,
                                const int* __restrict__ src_lens,
                                const float* __restrict__ durations,
                                const float* __restrict__ mus,
                                const float* __restrict__ log_vars,
                                const int* __restrict__ step_p,
                                float* __restrict__ out) {
    __shared__ float s_kl[8];
    __shared__ float s_dur[B_];
    __shared__ float s_d[KB_];

    int t    = threadIdx.x;      // 256 threads
    int lane = t & 31;
    int w    = t >> 5;

    {
        float lv = log_vars[t];
        float mu = mus[t];
        float kl = 1.f + lv - mu * mu - expf(lv);
        #pragma unroll
        for (int o = 16; o; o >>= 1) kl += __shfl_xor_sync(0xffffffffu, kl, o);
        if (lane == 0) s_kl[w] = kl;
    }

    {
        float ds = durations[w * S_ + lane] + durations[w * S_ + 32 + lane]
                 + durations[w * S_ + 64 + lane] + durations[w * S_ + 96 + lane];
        #pragma unroll
        for (int o = 16; o; o >>= 1) ds += __shfl_xor_sync(0xffffffffu, ds, o);
        if (lane == 0) s_dur[w] = ds;
    }

    if (t < KB_) s_d[t] = g_d[t];
    __syncthreads();

    if (t == 0) {
        float klsum = 0.f;
        #pragma unroll
        for (int i = 0; i < 8; i++) klsum += s_kl[i];
        float kl_loss = -0.5f * klsum;

        float sum_d = 0.f;
        #pragma unroll
        for (int p = 0; p < KB_; p++) sum_d += s_d[p];
        float mel_iter_loss = sum_d / (float)B_;

        float mel = 0.f, durl = 0.f;
        #pragma unroll
        for (int b = 0; b < B_; b++) {
            float len = (float)mel_lens[b];
            mel += mel_iter_loss / ((float)K_ * len);
            durl += fabsf(s_dur[b] - len) / (float)src_lens[b];
        }
        mel  /= (float)B_;
        durl  = 2.f * durl / (float)B_;

        int step = step_p[0];
        float beta;
        if (step < 2000)       beta = 0.f;
        else if (step >= 8000) beta = 1.f;
        else                   beta = (float)(step - 2000) / 6000.f;

        float total = mel + durl + beta * kl_loss;
        out[0] = total;
        out[1] = mel;
        out[2] = durl;
        out[3] = kl_loss;
        out[4] = beta;
    }
}

// ============================================================
extern "C" void kernel_launch(void* const* d_in, const int* in_sizes, int n_in,
                              void* d_out, int out_size) {
    const float* mel_iters   = (const float*)d_in[0];
    const float* mel_targets = (const float*)d_in[1];
    const int*   mel_lens    = (const int*)  d_in[2];
    const int*   src_lens    = (const int*)  d_in[3];
    const float* durations   = (const float*)d_in[4];
    const float* mus         = (const float*)d_in[5];
    const float* log_vars    = (const float*)d_in[6];
    const int*   step        = (const int*)  d_in[7];
    float*       out         = (float*)d_out;

    (void)in_sizes; (void)n_in; (void)out_size;

    const int total_rows = KB_ * N_ + B_ * N_;
    const int wpb = 8;
    prep_kernel<<<(total_rows + wpb - 1) / wpb, wpb * 32>>>(mel_iters, mel_targets);

    dim3 g((N_ + 63) / 64, (N_ + 63) / 64, KB_);
    dist_gemm_kernel<<<g, 256>>>();

    dtw_kernel<<<KB_, 800>>>();

    finalize_kernel<<<1, 256>>>(mel_lens, src_lens, durations, mus, log_vars, step, out);
}

// round 7
// speedup vs baseline: 1.6709x; 1.6709x over previous
#include <cuda_runtime.h>
#include <math.h>

#define BIGV   100000000.0f
#define GAMMA_ 0.05f
#define INVG_  20.0f
#define WARPP  256.0f
#define K_     4
#define B_     8
#define KB_    32
#define N_     800
#define C_     80
#define S_     128
#define Z_     32

// ---- scratch (device globals; no runtime allocation) ----
__device__ float g_sx[(size_t)KB_ * N_ * C_];   // sigmoid(mel_iters)
__device__ float g_sy[(size_t)B_  * N_ * C_];   // sigmoid(mel_targets)
__device__ float g_x2[KB_ * N_];                // row norms of sx
__device__ float g_y2[B_  * N_];                // row norms of sy
__device__ float g_D [(size_t)KB_ * N_ * N_];   // distance matrices
__device__ float g_d [KB_];                     // DTW costs

// ============================================================
// Kernel 1: sigmoid + squared row norms. One warp per row.
// (identical to 970us version)
// ============================================================
__global__ void prep_kernel(const float* __restrict__ mel_iters,
                            const float* __restrict__ mel_targets) {
    int wid  = (blockIdx.x * blockDim.x + threadIdx.x) >> 5;
    int lane = threadIdx.x & 31;
    const int xrows = KB_ * N_;
    const int total = xrows + B_ * N_;
    if (wid >= total) return;

    const float* src;
    float* dst;
    float* nrm;
    if (wid < xrows) {
        src = mel_iters + (size_t)wid * C_;
        dst = g_sx      + (size_t)wid * C_;
        nrm = g_x2 + wid;
    } else {
        int r = wid - xrows;
        src = mel_targets + (size_t)r * C_;
        dst = g_sy        + (size_t)r * C_;
        nrm = g_y2 + r;
    }
    float acc = 0.f;
    for (int c = lane; c < C_; c += 32) {
        float v = src[c];
        float s = 1.f / (1.f + expf(-v));
        dst[c] = s;
        acc += s * s;
    }
    #pragma unroll
    for (int o = 16; o; o >>= 1) acc += __shfl_xor_sync(0xffffffffu, acc, o);
    if (lane == 0) *nrm = acc;
}

// ============================================================
// Kernel 2: D[kb][n][m] = x2[n] + y2[m] - 2 * <sx[n], sy[m]>
// (identical to 970us version)
// ============================================================
__global__ void __launch_bounds__(256) dist_gemm_kernel() {
    __shared__ float sA[80 * 65];
    __shared__ float sB[80 * 65];

    const int kb = blockIdx.z;
    const int b  = kb & 7;
    const int m0 = blockIdx.x * 64;
    const int n0 = blockIdx.y * 64;
    const int t  = threadIdx.x;

    const float* xbase = g_sx + (size_t)kb * N_ * C_ + (size_t)n0 * C_;
    const float* ybase = g_sy + (size_t)b  * N_ * C_ + (size_t)m0 * C_;

    for (int e = t; e < 64 * 80; e += 256) {
        int r = e / 80;
        int c = e - r * 80;
        float xv = (n0 + r < N_) ? xbase[r * C_ + c] : 0.f;
        float yv = (m0 + r < N_) ? ybase[r * C_ + c] : 0.f;
        sA[c * 65 + r] = xv;
        sB[c * 65 + r] = yv;
    }
    __syncthreads();

    const int tx = t & 15;
    const int ty = t >> 4;

    float acc[4][4];
    #pragma unroll
    for (int i = 0; i < 4; i++)
        #pragma unroll
        for (int j = 0; j < 4; j++) acc[i][j] = 0.f;

    #pragma unroll 8
    for (int k = 0; k < 80; k++) {
        float a[4], bb[4];
        #pragma unroll
        for (int i = 0; i < 4; i++) a[i]  = sA[k * 65 + ty * 4 + i];
        #pragma unroll
        for (int j = 0; j < 4; j++) bb[j] = sB[k * 65 + tx * 4 + j];
        #pragma unroll
        for (int i = 0; i < 4; i++)
            #pragma unroll
            for (int j = 0; j < 4; j++)
                acc[i][j] = fmaf(a[i], bb[j], acc[i][j]);
    }

    float* Dp = g_D + (size_t)kb * N_ * N_;
    #pragma unroll
    for (int i = 0; i < 4; i++) {
        int n = n0 + ty * 4 + i;
        if (n >= N_) continue;
        float xn = g_x2[kb * N_ + n];
        int mbase = m0 + tx * 4;
        if (mbase + 3 < N_) {
            float4 v;
            v.x = xn + g_y2[b * N_ + mbase + 0] - 2.f * acc[i][0];
            v.y = xn + g_y2[b * N_ + mbase + 1] - 2.f * acc[i][1];
            v.z = xn + g_y2[b * N_ + mbase + 2] - 2.f * acc[i][2];
            v.w = xn + g_y2[b * N_ + mbase + 3] - 2.f * acc[i][3];
            *reinterpret_cast<float4*>(&Dp[(size_t)n * N_ + mbase]) = v;
        } else {
            #pragma unroll
            for (int j = 0; j < 4; j++) {
                int m = mbase + j;
                if (m < N_)
                    Dp[(size_t)n * N_ + m] = xn + g_y2[b * N_ + m] - 2.f * acc[i][j];
            }
        }
    }
}

// ============================================================
// Kernel 3: soft-DTW wavefront, barrier-per-diagonal (proven
// structure), RPT=2: 400 threads, thread t owns rows 2t+1,2t+2.
// Inner-row deps in registers; one smem boundary (ping-pong)
// per thread per diagonal. D prefetched 4 diagonals ahead.
// Softmin slow path uses __expf/__logf (single MUFU ops).
// ============================================================
#define NT2_ 400

__device__ __forceinline__ float softmin3(float a, float bu, float c) {
    float m = fminf(a, fminf(bu, c));
    float d1 = a - m, d2 = bu - m, d3 = c - m;
    float second = d1 + d2 + d3 - fmaxf(d1, fmaxf(d2, d3));
    float sm = m;
    if (second < 1.0f) {
        sm = m - GAMMA_ * __logf(__expf(-d1 * INVG_) +
                                 __expf(-d2 * INVG_) +
                                 __expf(-d3 * INVG_));
    }
    return sm;
}

__global__ void __launch_bounds__(NT2_) dtw_kernel() {
    __shared__ float bnd[2][NT2_];    // bnd[p][t] = row 2t+2 value at diag parity p

    const int kb = blockIdx.x;
    const int t  = threadIdx.x;
    const int i0 = 2 * t + 1;         // lower row (1-indexed)
    const int i1 = 2 * t + 2;         // upper row

    bnd[0][t] = BIGV;
    bnd[1][t] = BIGV;
    __syncthreads();

    // per-row DP state (diag d-1 and d-2 values)
    float one0 = BIGV, one1 = BIGV, two0 = BIGV, two1 = BIGV;
    float b_one = BIGV;               // row 2t @ d-1 (carried from smem read)

    const float* Drow0 = g_D + (size_t)kb * N_ * N_ + (size_t)(i0 - 1) * N_ - 1;
    const float* Drow1 = g_D + (size_t)kb * N_ * N_ + (size_t)(i1 - 1) * N_ - 1;
    #define CLAMP_J(jj) ( (jj) < 1 ? 1 : ((jj) > N_ ? N_ : (jj)) )

    // prefetch D for first 4 diagonals (both rows)
    float c0a, c1a, c2a, c3a;   // row i0, diags d0..d0+3
    float c0b, c1b, c2b, c3b;   // row i1
    {
        int ja = 2 - i0;
        int jb = 2 - i1;
        c0a = __ldg(Drow0 + CLAMP_J(ja + 0));
        c1a = __ldg(Drow0 + CLAMP_J(ja + 1));
        c2a = __ldg(Drow0 + CLAMP_J(ja + 2));
        c3a = __ldg(Drow0 + CLAMP_J(ja + 3));
        c0b = __ldg(Drow1 + CLAMP_J(jb + 0));
        c1b = __ldg(Drow1 + CLAMP_J(jb + 1));
        c2b = __ldg(Drow1 + CLAMP_J(jb + 2));
        c3b = __ldg(Drow1 + CLAMP_J(jb + 3));
    }

    for (int d0 = 2; d0 <= 2 * N_; d0 += 4) {
        // prefetch next group
        int jna = d0 + 4 - i0;
        int jnb = d0 + 4 - i1;
        float n0a = __ldg(Drow0 + CLAMP_J(jna + 0));
        float n1a = __ldg(Drow0 + CLAMP_J(jna + 1));
        float n2a = __ldg(Drow0 + CLAMP_J(jna + 2));
        float n3a = __ldg(Drow0 + CLAMP_J(jna + 3));
        float n0b = __ldg(Drow1 + CLAMP_J(jnb + 0));
        float n1b = __ldg(Drow1 + CLAMP_J(jnb + 1));
        float n2b = __ldg(Drow1 + CLAMP_J(jnb + 2));
        float n3b = __ldg(Drow1 + CLAMP_J(jnb + 3));

        #pragma unroll
        for (int r = 0; r < 4; r++) {
            int d = d0 + r;
            if (d <= 2 * N_) {                       // block-uniform guard
                // boundary: row 2t values. t=0 -> row 0 constants.
                float b_one_new;
                if (t == 0) b_one_new = BIGV;                       // R[0][j>=1] = BIG
                else        b_one_new = bnd[(d - 1) & 1][t - 1];    // row 2t @ d-1
                float b_two = (t == 0) ? ((d == 2) ? 0.f : BIGV) : b_one;

                // cell (i0, j0): diag arm row 2t
                int j0 = d - i0;
                float new0 = BIGV;
                if (j0 >= 1 && j0 <= N_) {
                    float Dv = (r == 0) ? c0a : (r == 1) ? c1a : (r == 2) ? c2a : c3a;
                    new0 = Dv + softmin3(b_two, b_one_new + WARPP, one0 + WARPP);
                }

                // cell (i1, j1): all arms in-register
                int j1 = d - i1;
                float new1 = BIGV;
                if (j1 >= 1 && j1 <= N_) {
                    float Dv = (r == 0) ? c0b : (r == 1) ? c1b : (r == 2) ? c2b : c3b;
                    new1 = Dv + softmin3(two0, one0 + WARPP, one1 + WARPP);
                }

                two0 = one0; two1 = one1;
                one0 = new0; one1 = new1;
                b_one = b_one_new;

                bnd[d & 1][t] = new1;                 // publish top row @ diag d
                __syncthreads();
            }
        }

        c0a = n0a; c1a = n1a; c2a = n2a; c3a = n3a;
        c0b = n0b; c1b = n1b; c2b = n2b; c3b = n3b;
    }

    // R[N][N] computed at d = 2N by thread NT2_-1, row i1 = N
    if (t == NT2_ - 1) g_d[kb] = one1;
    #undef CLAMP_J
}

// ============================================================
// Kernel 4: finalize scalar losses (parallel, measured ~6.5us).
// ============================================================
__global__ void finalize_kernel(const int* __restrict__ mel_lens,
                                const int* __restrict__ src_lens,
                                const float* __restrict__ durations,
                                const float* __restrict__ mus,
                                const float* __restrict__ log_vars,
                                const int* __restrict__ step_p,
                                float* __restrict__ out) {
    __shared__ float s_kl[8];
    __shared__ float s_dur[B_];
    __shared__ float s_d[KB_];

    int t    = threadIdx.x;      // 256 threads
    int lane = t & 31;
    int w    = t >> 5;

    {
        float lv = log_vars[t];
        float mu = mus[t];
        float kl = 1.f + lv - mu * mu - expf(lv);
        #pragma unroll
        for (int o = 16; o; o >>= 1) kl += __shfl_xor_sync(0xffffffffu, kl, o);
        if (lane == 0) s_kl[w] = kl;
    }

    {
        float ds = durations[w * S_ + lane] + durations[w * S_ + 32 + lane]
                 + durations[w * S_ + 64 + lane] + durations[w * S_ + 96 + lane];
        #pragma unroll
        for (int o = 16; o; o >>= 1) ds += __shfl_xor_sync(0xffffffffu, ds, o);
        if (lane == 0) s_dur[w] = ds;
    }

    if (t < KB_) s_d[t] = g_d[t];
    __syncthreads();

    if (t == 0) {
        float klsum = 0.f;
        #pragma unroll
        for (int i = 0; i < 8; i++) klsum += s_kl[i];
        float kl_loss = -0.5f * klsum;

        float sum_d = 0.f;
        #pragma unroll
        for (int p = 0; p < KB_; p++) sum_d += s_d[p];
        float mel_iter_loss = sum_d / (float)B_;

        float mel = 0.f, durl = 0.f;
        #pragma unroll
        for (int b = 0; b < B_; b++) {
            float len = (float)mel_lens[b];
            mel += mel_iter_loss / ((float)K_ * len);
            durl += fabsf(s_dur[b] - len) / (float)src_lens[b];
        }
        mel  /= (float)B_;
        durl  = 2.f * durl / (float)B_;

        int step = step_p[0];
        float beta;
        if (step < 2000)       beta = 0.f;
        else if (step >= 8000) beta = 1.f;
        else                   beta = (float)(step - 2000) / 6000.f;

        float total = mel + durl + beta * kl_loss;
        out[0] = total;
        out[1] = mel;
        out[2] = durl;
        out[3] = kl_loss;
        out[4] = beta;
    }
}

// ============================================================
extern "C" void kernel_launch(void* const* d_in, const int* in_sizes, int n_in,
                              void* d_out, int out_size) {
    const float* mel_iters   = (const float*)d_in[0];
    const float* mel_targets = (const float*)d_in[1];
    const int*   mel_lens    = (const int*)  d_in[2];
    const int*   src_lens    = (const int*)  d_in[3];
    const float* durations   = (const float*)d_in[4];
    const float* mus         = (const float*)d_in[5];
    const float* log_vars    = (const float*)d_in[6];
    const int*   step        = (const int*)  d_in[7];
    float*       out         = (float*)d_out;

    (void)in_sizes; (void)n_in; (void)out_size;

    const int total_rows = KB_ * N_ + B_ * N_;
    const int wpb = 8;
    prep_kernel<<<(total_rows + wpb - 1) / wpb, wpb * 32>>>(mel_iters, mel_targets);

    dim3 g((N_ + 63) / 64, (N_ + 63) / 64, KB_);
    dist_gemm_kernel<<<g, 256>>>();

    dtw_kernel<<<KB_, NT2_>>>();

    finalize_kernel<<<1, 256>>>(mel_lens, src_lens, durations, mus, log_vars, step, out);
}

// round 8
// speedup vs baseline: 2.3330x; 1.3963x over previous
#include <cuda_runtime.h>
#include <math.h>

#define BIGV   100000000.0f
#define GAMMA_ 0.05f
#define INVG_  20.0f
#define WARPP  256.0f
#define K_     4
#define B_     8
#define KB_    32
#define N_     800
#define C_     80
#define S_     128
#define Z_     32

// diagonal-major D: g_Dd[kb][d-2][n] = D[n][m], d-2 = n+m (0-indexed)
// rows padded to 1608 so 4-ahead prefetch never reads past the end
#define DDROWS_ 1608

// ---- scratch (device globals; no runtime allocation) ----
__device__ float g_sx[(size_t)KB_ * N_ * C_];   // sigmoid(mel_iters)
__device__ float g_sy[(size_t)B_  * N_ * C_];   // sigmoid(mel_targets)
__device__ float g_x2[KB_ * N_];                // row norms of sx
__device__ float g_y2[B_  * N_];                // row norms of sy
__device__ float g_Dd[(size_t)KB_ * DDROWS_ * N_];  // diagonal-major distances
__device__ float g_d [KB_];                     // DTW costs

// ============================================================
// Kernel 1: sigmoid + squared row norms. One warp per row.
// ============================================================
__global__ void prep_kernel(const float* __restrict__ mel_iters,
                            const float* __restrict__ mel_targets) {
    int wid  = (blockIdx.x * blockDim.x + threadIdx.x) >> 5;
    int lane = threadIdx.x & 31;
    const int xrows = KB_ * N_;
    const int total = xrows + B_ * N_;
    if (wid >= total) return;

    const float* src;
    float* dst;
    float* nrm;
    if (wid < xrows) {
        src = mel_iters + (size_t)wid * C_;
        dst = g_sx      + (size_t)wid * C_;
        nrm = g_x2 + wid;
    } else {
        int r = wid - xrows;
        src = mel_targets + (size_t)r * C_;
        dst = g_sy        + (size_t)r * C_;
        nrm = g_y2 + r;
    }
    float acc = 0.f;
    for (int c = lane; c < C_; c += 32) {
        float v = src[c];
        float s = 1.f / (1.f + expf(-v));
        dst[c] = s;
        acc += s * s;
    }
    #pragma unroll
    for (int o = 16; o; o >>= 1) acc += __shfl_xor_sync(0xffffffffu, acc, o);
    if (lane == 0) *nrm = acc;
}

// ============================================================
// Kernel 2: distance GEMM with diagonal-major epilogue.
// Mainloop identical to the proven 970us version. Epilogue
// re-stages the 64x64 result tile into smem (stride 66 ->
// anti-diagonal reads have lane stride 65 = conflict-free),
// then writes Dd[n+m][n] in coalesced runs of up to 64 floats.
// ============================================================
__global__ void __launch_bounds__(256) dist_gemm_kernel() {
    __shared__ float sA[80 * 65];
    __shared__ float sB[80 * 65];

    const int kb = blockIdx.z;
    const int b  = kb & 7;
    const int m0 = blockIdx.x * 64;
    const int n0 = blockIdx.y * 64;
    const int t  = threadIdx.x;

    const float* xbase = g_sx + (size_t)kb * N_ * C_ + (size_t)n0 * C_;
    const float* ybase = g_sy + (size_t)b  * N_ * C_ + (size_t)m0 * C_;

    for (int e = t; e < 64 * 80; e += 256) {
        int r = e / 80;
        int c = e - r * 80;
        float xv = (n0 + r < N_) ? xbase[r * C_ + c] : 0.f;
        float yv = (m0 + r < N_) ? ybase[r * C_ + c] : 0.f;
        sA[c * 65 + r] = xv;
        sB[c * 65 + r] = yv;
    }
    __syncthreads();

    const int tx = t & 15;
    const int ty = t >> 4;

    float acc[4][4];
    #pragma unroll
    for (int i = 0; i < 4; i++)
        #pragma unroll
        for (int j = 0; j < 4; j++) acc[i][j] = 0.f;

    #pragma unroll 8
    for (int k = 0; k < 80; k++) {
        float a[4], bb[4];
        #pragma unroll
        for (int i = 0; i < 4; i++) a[i]  = sA[k * 65 + ty * 4 + i];
        #pragma unroll
        for (int j = 0; j < 4; j++) bb[j] = sB[k * 65 + tx * 4 + j];
        #pragma unroll
        for (int i = 0; i < 4; i++)
            #pragma unroll
            for (int j = 0; j < 4; j++)
                acc[i][j] = fmaf(a[i], bb[j], acc[i][j]);
    }

    // ---- epilogue: D values -> smem tile (stride 66) ----
    __syncthreads();                 // all sA/sB reads done; alias sA as sD
    float* sD = sA;                  // needs 64*66 = 4224 <= 80*65 = 5200

    {
        int nb = ty * 4, mb = tx * 4;
        float xn[4], ym[4];
        #pragma unroll
        for (int ii = 0; ii < 4; ii++) {
            int n = n0 + nb + ii;
            int m = m0 + mb + ii;
            xn[ii] = g_x2[kb * N_ + (n < N_ ? n : N_ - 1)];
            ym[ii] = g_y2[b  * N_ + (m < N_ ? m : N_ - 1)];
        }
        #pragma unroll
        for (int ii = 0; ii < 4; ii++)
            #pragma unroll
            for (int jj = 0; jj < 4; jj++)
                sD[(nb + ii) * 66 + (mb + jj)] = xn[ii] + ym[jj] - 2.f * acc[ii][jj];
    }
    __syncthreads();

    // ---- write 127 local anti-diagonals, coalesced in n ----
    {
        const int w8   = t >> 5;
        const int lane = t & 31;
        float* DdBase = g_Dd + (size_t)kb * ((size_t)DDROWS_ * N_);
        for (int ld = w8; ld < 127; ld += 8) {
            int nlo = ld > 63 ? ld - 63 : 0;
            int nhi = ld < 63 ? ld : 63;
            for (int nl = nlo + lane; nl <= nhi; nl += 32) {
                int ml = ld - nl;
                int n = n0 + nl, m = m0 + ml;
                if (n < N_ && m < N_)
                    DdBase[(size_t)(n + m) * N_ + n] = sD[nl * 66 + ml];
            }
        }
    }
}

// ============================================================
// Kernel 3: soft-DTW wavefront, barrier-per-diagonal, RPT=2
// (400 threads, thread t owns rows 2t+1, 2t+2). D loads are now
// COALESCED float2 from diagonal-major g_Dd (2 lines per warp
// per diagonal instead of 64). Prefetched 4 diagonals ahead.
// ============================================================
#define NT2_ 400

__device__ __forceinline__ float softmin3(float a, float bu, float c) {
    float m = fminf(a, fminf(bu, c));
    float d1 = a - m, d2 = bu - m, d3 = c - m;
    float second = d1 + d2 + d3 - fmaxf(d1, fmaxf(d2, d3));
    float sm = m;
    if (second < 1.0f) {
        sm = m - GAMMA_ * __logf(__expf(-d1 * INVG_) +
                                 __expf(-d2 * INVG_) +
                                 __expf(-d3 * INVG_));
    }
    return sm;
}

__global__ void __launch_bounds__(NT2_) dtw_kernel() {
    __shared__ float bnd[2][NT2_];    // bnd[p][t] = row 2t+2 value at diag parity p

    const int kb = blockIdx.x;
    const int t  = threadIdx.x;
    const int i0 = 2 * t + 1;         // lower row (1-indexed)
    const int i1 = 2 * t + 2;         // upper row

    bnd[0][t] = BIGV;
    bnd[1][t] = BIGV;
    __syncthreads();

    float one0 = BIGV, one1 = BIGV, two0 = BIGV, two1 = BIGV;
    float b_one = BIGV;               // row 2t @ d-1 (carried)

    // float2 view: row r (= d-2), element pair (2t, 2t+1) -> (.x=i0, .y=i1)
    const float2* Dd2 = (const float2*)g_Dd + (size_t)kb * ((size_t)DDROWS_ * (N_ / 2));

    // prefetch D for first 4 diagonals (rows 0..3)
    float2 cur0 = Dd2[(size_t)0 * (N_/2) + t];
    float2 cur1 = Dd2[(size_t)1 * (N_/2) + t];
    float2 cur2 = Dd2[(size_t)2 * (N_/2) + t];
    float2 cur3 = Dd2[(size_t)3 * (N_/2) + t];

    for (int d0 = 2; d0 <= 2 * N_; d0 += 4) {
        // prefetch next group: rows d0+2 .. d0+5  (max 1603 < DDROWS_)
        size_t rbase = (size_t)(d0 + 2) * (N_/2) + t;
        float2 nx0 = Dd2[rbase + 0 * (N_/2)];
        float2 nx1 = Dd2[rbase + 1 * (N_/2)];
        float2 nx2 = Dd2[rbase + 2 * (N_/2)];
        float2 nx3 = Dd2[rbase + 3 * (N_/2)];

        #pragma unroll
        for (int r = 0; r < 4; r++) {
            int d = d0 + r;
            if (d <= 2 * N_) {                       // block-uniform guard
                float b_one_new;
                if (t == 0) b_one_new = BIGV;                       // R[0][j>=1] = BIG
                else        b_one_new = bnd[(d - 1) & 1][t - 1];    // row 2t @ d-1
                float b_two = (t == 0) ? ((d == 2) ? 0.f : BIGV) : b_one;

                float2 Dv = (r == 0) ? cur0 : (r == 1) ? cur1 : (r == 2) ? cur2 : cur3;

                // cell (i0, j0)
                int j0 = d - i0;
                float new0 = BIGV;
                if (j0 >= 1 && j0 <= N_)
                    new0 = Dv.x + softmin3(b_two, b_one_new + WARPP, one0 + WARPP);

                // cell (i1, j1): all arms in-register
                int j1 = d - i1;
                float new1 = BIGV;
                if (j1 >= 1 && j1 <= N_)
                    new1 = Dv.y + softmin3(two0, one0 + WARPP, one1 + WARPP);

                two0 = one0; two1 = one1;
                one0 = new0; one1 = new1;
                b_one = b_one_new;

                bnd[d & 1][t] = new1;                 // publish top row @ diag d
                __syncthreads();
            }
        }

        cur0 = nx0; cur1 = nx1; cur2 = nx2; cur3 = nx3;
    }

    // R[N][N] computed at d = 2N by thread NT2_-1, row i1 = N
    if (t == NT2_ - 1) g_d[kb] = one1;
}

// ============================================================
// Kernel 4: finalize scalar losses (parallel, ~6.5us).
// ============================================================
__global__ void finalize_kernel(const int* __restrict__ mel_lens,
                                const int* __restrict__ src_lens,
                                const float* __restrict__ durations,
                                const float* __restrict__ mus,
                                const float* __restrict__ log_vars,
                                const int* __restrict__ step_p,
                                float* __restrict__ out) {
    __shared__ float s_kl[8];
    __shared__ float s_dur[B_];
    __shared__ float s_d[KB_];

    int t    = threadIdx.x;      // 256 threads
    int lane = t & 31;
    int w    = t >> 5;

    {
        float lv = log_vars[t];
        float mu = mus[t];
        float kl = 1.f + lv - mu * mu - expf(lv);
        #pragma unroll
        for (int o = 16; o; o >>= 1) kl += __shfl_xor_sync(0xffffffffu, kl, o);
        if (lane == 0) s_kl[w] = kl;
    }

    {
        float ds = durations[w * S_ + lane] + durations[w * S_ + 32 + lane]
                 + durations[w * S_ + 64 + lane] + durations[w * S_ + 96 + lane];
        #pragma unroll
        for (int o = 16; o; o >>= 1) ds += __shfl_xor_sync(0xffffffffu, ds, o);
        if (lane == 0) s_dur[w] = ds;
    }

    if (t < KB_) s_d[t] = g_d[t];
    __syncthreads();

    if (t == 0) {
        float klsum = 0.f;
        #pragma unroll
        for (int i = 0; i < 8; i++) klsum += s_kl[i];
        float kl_loss = -0.5f * klsum;

        float sum_d = 0.f;
        #pragma unroll
        for (int p = 0; p < KB_; p++) sum_d += s_d[p];
        float mel_iter_loss = sum_d / (float)B_;

        float mel = 0.f, durl = 0.f;
        #pragma unroll
        for (int b = 0; b < B_; b++) {
            float len = (float)mel_lens[b];
            mel += mel_iter_loss / ((float)K_ * len);
            durl += fabsf(s_dur[b] - len) / (float)src_lens[b];
        }
        mel  /= (float)B_;
        durl  = 2.f * durl / (float)B_;

        int step = step_p[0];
        float beta;
        if (step < 2000)       beta = 0.f;
        else if (step >= 8000) beta = 1.f;
        else                   beta = (float)(step - 2000) / 6000.f;

        float total = mel + durl + beta * kl_loss;
        out[0] = total;
        out[1] = mel;
        out[2] = durl;
        out[3] = kl_loss;
        out[4] = beta;
    }
}

// ============================================================
extern "C" void kernel_launch(void* const* d_in, const int* in_sizes, int n_in,
                              void* d_out, int out_size) {
    const float* mel_iters   = (const float*)d_in[0];
    const float* mel_targets = (const float*)d_in[1];
    const int*   mel_lens    = (const int*)  d_in[2];
    const int*   src_lens    = (const int*)  d_in[3];
    const float* durations   = (const float*)d_in[4];
    const float* mus         = (const float*)d_in[5];
    const float* log_vars    = (const float*)d_in[6];
    const int*   step        = (const int*)  d_in[7];
    float*       out         = (float*)d_out;

    (void)in_sizes; (void)n_in; (void)out_size;

    const int total_rows = KB_ * N_ + B_ * N_;
    const int wpb = 8;
    prep_kernel<<<(total_rows + wpb - 1) / wpb, wpb * 32>>>(mel_iters, mel_targets);

    dim3 g((N_ + 63) / 64, (N_ + 63) / 64, KB_);
    dist_gemm_kernel<<<g, 256>>>();

    dtw_kernel<<<KB_, NT2_>>>();

    finalize_kernel<<<1, 256>>>(mel_lens, src_lens, durations, mus, log_vars, step, out);
}